// round 1
// baseline (speedup 1.0000x reference)
#include <cuda_runtime.h>
#include <cstdint>

// Problem shapes (fixed by setup_inputs):
//   k_cache: (B=4, H=8, D=128, TILE=128, T=64) f32  -> (BH=32, D=128, SFULL=8192)
//   v_cache: (B=4, H=8, TILE=128, T=64, D=128) f32  -> (BH=32, SFULL=8192, D=128)
//   seq_len = 6144 (derived on host from out_size)
// Output: stack([transpose(k[:, :, :S]), v[:, :S, :]]) -> (2, BH, S, D) f32

#define BH_    32
#define D_     128
#define SFULL_ 8192

// ---------------------------------------------------------------------------
// K transpose: per (b,h), transpose (D=128, S) -> (S, D=128).
// 32x32 shared tile, padded to kill bank conflicts. Block (32,8), each thread
// handles 4 rows. Loads coalesced along S, stores coalesced along D.
// ---------------------------------------------------------------------------
__global__ void k_transpose_kernel(const float* __restrict__ kin,
                                   float* __restrict__ kout,
                                   int S) {
    __shared__ float tile[32][33];

    const int bh = blockIdx.z;
    const int d0 = blockIdx.y * 32;   // 0..96
    const int s0 = blockIdx.x * 32;   // 0..S-32

    const float* src = kin + (size_t)bh * D_ * SFULL_;
    float*       dst = kout + (size_t)bh * S * D_;

    const int tx = threadIdx.x;       // 0..31
    const int ty = threadIdx.y;       // 0..7

    // Load: rows = d, cols = s (contiguous)
#pragma unroll
    for (int i = 0; i < 32; i += 8) {
        tile[ty + i][tx] = src[(size_t)(d0 + ty + i) * SFULL_ + (s0 + tx)];
    }
    __syncthreads();

    // Store: rows = s, cols = d (contiguous)
#pragma unroll
    for (int i = 0; i < 32; i += 8) {
        dst[(size_t)(s0 + ty + i) * D_ + (d0 + tx)] = tile[tx][ty + i];
    }
}

// ---------------------------------------------------------------------------
// V copy: per (b,h), copy the first S*D floats of each SFULL*D block.
// float4-vectorized; grid.y = bh, grid.x strides over the per-(b,h) chunk.
// ---------------------------------------------------------------------------
__global__ void v_copy_kernel(const float4* __restrict__ vin,
                              float4* __restrict__ vout,
                              int S) {
    const int    bh      = blockIdx.y;
    const size_t per_out = (size_t)S * D_ / 4;       // float4 per (b,h) chunk
    const size_t per_in  = (size_t)SFULL_ * D_ / 4;

    const float4* src = vin + (size_t)bh * per_in;
    float4*       dst = vout + (size_t)bh * per_out;

    const size_t stride = (size_t)gridDim.x * blockDim.x;
    for (size_t i = (size_t)blockIdx.x * blockDim.x + threadIdx.x;
         i < per_out; i += stride) {
        dst[i] = src[i];
    }
}

extern "C" void kernel_launch(void* const* d_in, const int* in_sizes, int n_in,
                              void* d_out, int out_size) {
    const float* k_cache = (const float*)d_in[0];
    const float* v_cache = (const float*)d_in[1];
    // d_in[2] is seq_len on device; derive it from out_size instead
    // (out = 2 * BH * S * D elements).
    const int S = out_size / (2 * BH_ * D_);   // 6144 for this instance

    float* out_k = (float*)d_out;                                 // (BH, S, D)
    float* out_v = (float*)d_out + (size_t)BH_ * S * D_;          // (BH, S, D)

    // K transpose: grid (S/32, D/32, BH), block (32,8)
    {
        dim3 block(32, 8, 1);
        dim3 grid((unsigned)(S / 32), D_ / 32, BH_);
        k_transpose_kernel<<<grid, block>>>(k_cache, out_k, S);
    }

    // V copy: per-(b,h) chunk = S*D/4 float4 = 196608; 192 blocks x 256 thr
    // -> 4 float4 per thread.
    {
        dim3 block(256, 1, 1);
        dim3 grid(192, BH_, 1);
        v_copy_kernel<<<grid, block>>>((const float4*)v_cache, (float4*)out_v, S);
    }
}

// round 2
// speedup vs baseline: 1.0934x; 1.0934x over previous
#include <cuda_runtime.h>
#include <cstdint>

// Shapes (fixed by setup_inputs):
//   k_cache: (B=4, H=8, D=128, 128, 64) f32 -> (BH=32, D=128, SFULL=8192)
//   v_cache: (B=4, H=8, 128, 64, D=128) f32 -> (BH=32, SFULL=8192, D=128)
//   S = 6144 (derived from out_size)
// out = stack([transpose_k(:, :, :S), v(:, :S, :)]) -> (2, BH, S, D)

#define BH_    32
#define D_     128
#define SFULL_ 8192

// One fused kernel. Even blocks: K-transpose tile (d=128 x s=32, 16 KB in /
// 16 KB contiguous out). Odd blocks: V copy of 1024 float4 (16 KB).
// Block counts per (b,h) are identical for both halves (S/32), so the flat
// id decomposes the same way for either type.
__global__ __launch_bounds__(256) void fused_kv_kernel(
    const float*  __restrict__ kin,
    const float4* __restrict__ vin,
    float*        __restrict__ outk,
    float4*       __restrict__ outv,
    int S, int tilesPerBh)
{
    const int b  = blockIdx.x;
    const int t  = threadIdx.x;
    const int id = b >> 1;
    const int bh = id / tilesPerBh;
    const int jj = id - bh * tilesPerBh;

    if (b & 1) {
        // ------------------ V copy: contiguous 16 KB chunk ------------------
        const float4* src = vin  + (size_t)bh * (SFULL_ * (D_ / 4)) + (size_t)jj * 1024;
        float4*       dst = outv + (size_t)bh * ((size_t)S * (D_ / 4)) + (size_t)jj * 1024;
#pragma unroll
        for (int i = 0; i < 4; ++i)
            dst[t + i * 256] = src[t + i * 256];
    } else {
        // --------------- K transpose: (D=128, s=32) -> (s=32, D=128) --------
        // tile[s][d], row stride 129 floats:
        //   STS bank = (4f+k+d) mod 32  -> conflict-free per warp
        //   LDS bank = (s+d)    mod 32  -> conflict-free per warp
        __shared__ float tile[32][129];

        const int s0 = jj * 32;
        const float* src = kin  + (size_t)bh * D_ * SFULL_ + s0;
        float*       dst = outk + (size_t)bh * (size_t)S * D_ + (size_t)s0 * D_;

        // Load: 1024 float4; warp covers 4 d-rows x 128 B each (coalesced).
#pragma unroll
        for (int i = 0; i < 4; ++i) {
            const int idx = t + i * 256;
            const int d = idx >> 3;       // 0..127
            const int f = idx & 7;        // float4 index along s
            float4 val = *(const float4*)(src + (size_t)d * SFULL_ + 4 * f);
            tile[4 * f + 0][d] = val.x;
            tile[4 * f + 1][d] = val.y;
            tile[4 * f + 2][d] = val.z;
            tile[4 * f + 3][d] = val.w;
        }
        __syncthreads();

        // Store: 4096 scalars; each warp writes a contiguous 128 B segment,
        // block writes a fully contiguous 16 KB region of the output.
#pragma unroll
        for (int i = 0; i < 16; ++i) {
            const int e = t + i * 256;
            const int s = e >> 7;         // 0..31
            const int d = e & 127;        // 0..127
            dst[(size_t)s * D_ + d] = tile[s][d];
        }
    }
}

extern "C" void kernel_launch(void* const* d_in, const int* in_sizes, int n_in,
                              void* d_out, int out_size) {
    const float* k_cache = (const float*)d_in[0];
    const float* v_cache = (const float*)d_in[1];
    // seq_len is fully determined by out_size: out = 2 * BH * S * D elems.
    const int S = out_size / (2 * BH_ * D_);        // 6144
    const int tilesPerBh = S / 32;                  // 192

    float*  out_k = (float*)d_out;                                  // (BH,S,D)
    float4* out_v = (float4*)((float*)d_out + (size_t)BH_ * S * D_);

    dim3 block(256, 1, 1);
    dim3 grid((unsigned)(2 * BH_ * tilesPerBh), 1, 1);              // 12288
    fused_kv_kernel<<<grid, block>>>(k_cache, (const float4*)v_cache,
                                     out_k, out_v, S, tilesPerBh);
}